// round 8
// baseline (speedup 1.0000x reference)
#include <cuda_runtime.h>
#include <cuda_fp16.h>
#include <cstdint>

// ============================ PTX helpers (non-'a' target safe) ============================
__device__ __forceinline__ uint32_t smem_to_u32(const void* smem_ptr) {
    uint32_t addr;
    asm("{ .reg .u64 tmp; cvta.to.shared.u64 tmp, %1; cvt.u32.u64 %0, tmp; }"
        : "=r"(addr) : "l"(smem_ptr));
    return addr;
}

#define CP_ASYNC16(dst_u32, src_ptr) \
    asm volatile("cp.async.cg.shared.global [%0], [%1], 16;" \
                 :: "r"(dst_u32), "l"(src_ptr) : "memory")
#define CP_COMMIT() asm volatile("cp.async.commit_group;" ::: "memory")
#define CP_WAIT0()  asm volatile("cp.async.wait_group 0;" ::: "memory")

#define LDSM_X4(r0, r1, r2, r3, addr) \
    asm volatile("ldmatrix.sync.aligned.m8n8.x4.shared.b16 {%0,%1,%2,%3}, [%4];" \
                 : "=r"(r0), "=r"(r1), "=r"(r2), "=r"(r3) : "r"(addr))

#define MMA16816H(d, a, b0, b1) \
    asm volatile("mma.sync.aligned.m16n8k16.row.col.f32.f16.f16.f32 " \
                 "{%0,%1,%2,%3}, {%4,%5,%6,%7}, {%8,%9}, {%0,%1,%2,%3};" \
                 : "+f"((d)[0]), "+f"((d)[1]), "+f"((d)[2]), "+f"((d)[3]) \
                 : "r"((a)[0]), "r"((a)[1]), "r"((a)[2]), "r"((a)[3]), \
                   "r"(b0), "r"(b1))

__device__ __forceinline__ uint32_t swz128(uint32_t off) {
    return off ^ ((off >> 3) & 0x70);
}
__device__ __forceinline__ uint32_t pack_h2(__half a, __half b) {
    __half2 t = __halves2half2(a, b);  // a -> low 16 bits
    return *reinterpret_cast<uint32_t*>(&t);
}

// ============================ problem constants ============================
static constexpr int NTOK   = 8192;
static constexpr int FEAT   = 128;
static constexpr int KC     = 64;               // k per B-chunk
static constexpr int NCHUNK = NTOK / KC;        // 128
static constexpr int CHUNK_BYTES = FEAT * 128;  // 128 n-rows x 128B (64 k fp16) = 16384
static constexpr int TM     = 128;              // CTA M tile
static constexpr int TN     = 64;               // CTA N tile
static constexpr int KSTEP  = 64;
static constexpr int NSTAGE = NTOK / KSTEP;     // 128
// stage: [0,16K) A_hi | [16K,32K) A_lo | [32K,40K) B (fp16 single)
static constexpr int STG    = 40960;

// ============================ device scratch ============================
__device__ __align__(16) unsigned char g_B1[NCHUNK * CHUNK_BYTES];  // 2 MB fp16 xw^T chunks
__device__ __align__(16) unsigned char g_B2[NCHUNK * CHUNK_BYTES];  // 2 MB fp16 Z^T chunks
__device__ __align__(16) float g_scale[NTOK];

// ============================ kernel 1: xw = x @ W -> fp16 chunks ============================
// grid 128 x 256 thr; block does 64 rows. smem: W 64K + x 32K.
__global__ void xw_kernel(const float* __restrict__ x, const float* __restrict__ W) {
    extern __shared__ float sh[];
    float* Ws = sh;             // 128*128
    float* xs = sh + 16384;     // 64*128
    const int tid = threadIdx.x;
    const int rowbase = blockIdx.x * 64;

    for (int i = tid; i < 16384; i += 256) Ws[i] = W[i];
    for (int i = tid; i < 8192;  i += 256) xs[i] = x[(size_t)rowbase * 128 + i];
    __syncthreads();

    const int n  = tid & 127;
    const int rg = tid >> 7;    // 0..1 -> rows rg*32 .. rg*32+31
    #pragma unroll 1
    for (int rp = 0; rp < 16; rp++) {
        const int r0 = rg * 32 + 2 * rp;
        float a0 = 0.f, a1 = 0.f;
        const float* x0 = xs + r0 * 128;
        const float* x1 = x0 + 128;
        #pragma unroll 8
        for (int k = 0; k < 128; k++) {
            float w = Ws[k * 128 + n];
            a0 = fmaf(x0[k], w, a0);
            a1 = fmaf(x1[k], w, a1);
        }
        int kg = rowbase + r0;
        int chunk = kg >> 6;
        int c = kg & 63;
        uint32_t off = swz128((uint32_t)n * 128u + (uint32_t)c * 2u);
        *(uint32_t*)(g_B1 + (size_t)chunk * CHUNK_BYTES + off) =
            pack_h2(__float2half_rn(a0), __float2half_rn(a1));
    }
}

// ============================ kernel 2: scale = sum_j d^2 * f ============================
__global__ void scale_kernel(const float* __restrict__ d_list, const float* __restrict__ filt) {
    int n = blockIdx.x * 256 + threadIdx.x;
    float s = 0.f;
    #pragma unroll
    for (int j = 0; j < 3; j++) {
        float d = d_list[j * NTOK + n];
        float f = filt[j * NTOK + n];
        s = fmaf(d * d, f, s);
    }
    g_scale[n] = s;
}

// ============================ fused GEMM: 128x64 tile, fp16 2-product split ============================
// grid (64, 2), 128 threads (4 warps, 2m x 2n, warp tile 64x32), 2-stage pipeline.
__global__ __launch_bounds__(128, 1)
void gemm_fused_kernel(const float* __restrict__ A, const float* __restrict__ bias,
                       float* __restrict__ out, int phase) {
    extern __shared__ unsigned char dynsmem[];

    const unsigned char* B = phase ? g_B2 : g_B1;

    const int tid = threadIdx.x;
    const int wid = tid >> 5;
    const int lid = tid & 31;
    const int mb = blockIdx.x * TM;
    const int nb = blockIdx.y * TN;

    const int wm = (wid >> 1) * 64;   // 0 or 64
    const int wn = (wid & 1) * 32;    // 0 or 32

    uint32_t smem_u = smem_to_u32(dynsmem);
    uint32_t base = (smem_u + 1023u) & ~1023u;
    unsigned char* sb = dynsmem + (base - smem_u);

    float acc[4][4][4];   // mi (m16) x nj (n8) x 4
    #pragma unroll
    for (int i = 0; i < 4; i++)
        #pragma unroll
        for (int j = 0; j < 4; j++)
            #pragma unroll
            for (int q = 0; q < 4; q++) acc[i][j][q] = 0.f;

    float4 aReg[8];   // one half-stage of A (128 rows x 32 k fp32)

    auto ldg_half = [&](int s, int h) {
        #pragma unroll
        for (int i = 0; i < 8; i++) {
            int idx = tid + i * 128;      // 1024 float4 slots: 128 rows x 8
            int row = idx >> 3;
            int c4 = idx & 7;
            const float* src = A + (size_t)(mb + row) * NTOK + s * KSTEP + h * 32 + c4 * 4;
            aReg[i] = *reinterpret_cast<const float4*>(src);
        }
    };
    auto sts_half = [&](int st, int h) {
        unsigned char* stp = sb + st * STG;
        #pragma unroll
        for (int i = 0; i < 8; i++) {
            int idx = tid + i * 128;
            int row = idx >> 3;
            int c4 = idx & 7;
            uint32_t o = swz128((uint32_t)(row * 128 + h * 64 + c4 * 8));
            float4 v = aReg[i];
            __half hx = __float2half_rn(v.x);
            __half hy = __float2half_rn(v.y);
            __half hz = __float2half_rn(v.z);
            __half hw = __float2half_rn(v.w);
            __half lx = __float2half_rn(v.x - __half2float(hx));
            __half ly = __float2half_rn(v.y - __half2float(hy));
            __half lz = __float2half_rn(v.z - __half2float(hz));
            __half lw = __float2half_rn(v.w - __half2float(hw));
            *(uint2*)(stp + o)          = make_uint2(pack_h2(hx, hy), pack_h2(hz, hw));
            *(uint2*)(stp + 16384 + o)  = make_uint2(pack_h2(lx, ly), pack_h2(lz, lw));
        }
    };
    auto cpasync_b = [&](int s, int st) {
        uint32_t dst = base + st * STG + 32768;
        const unsigned char* src = B + (size_t)s * CHUNK_BYTES + nb * 128;  // 8KB contiguous
        #pragma unroll
        for (int i = 0; i < 4; i++) {
            int off = (tid + i * 128) * 16;
            CP_ASYNC16(dst + off, src + off);
        }
        CP_COMMIT();
    };

    // ldmatrix per-lane address components
    const int l7  = lid & 7;
    const int mat = lid >> 3;
    const int a_row_off = l7 + (mat & 1) * 8;
    const int a_kb_add  = (mat >> 1) * 16;
    const int b_row_off = l7 + (mat >> 1) * 8;
    const int b_kb_add  = (mat & 1) * 16;

    auto compute_kk = [&](int st, int kk) {
        uint32_t sA = base + st * STG;
        uint32_t sB = sA + 32768;
        const int kb = kk * 32;
        uint32_t ah[4][4], al[4][4], bf[4][2];
        #pragma unroll
        for (int mi = 0; mi < 4; mi++) {
            int row = wm + mi * 16 + a_row_off;
            uint32_t off = (uint32_t)(row * 128) + (uint32_t)((kb + a_kb_add) ^ ((row & 7) << 4));
            LDSM_X4(ah[mi][0], ah[mi][1], ah[mi][2], ah[mi][3], sA + off);
            LDSM_X4(al[mi][0], al[mi][1], al[mi][2], al[mi][3], sA + 16384 + off);
        }
        #pragma unroll
        for (int g = 0; g < 2; g++) {
            int row = wn + g * 16 + b_row_off;
            uint32_t off = (uint32_t)(row * 128) + (uint32_t)((kb + b_kb_add) ^ ((row & 7) << 4));
            uint32_t r0, r1, r2, r3;
            LDSM_X4(r0, r1, r2, r3, sB + off);
            bf[2 * g][0] = r0;     bf[2 * g][1] = r1;
            bf[2 * g + 1][0] = r2; bf[2 * g + 1][1] = r3;
        }
        // hi products then lo products (max acc-RAW distance)
        #pragma unroll
        for (int mi = 0; mi < 4; mi++)
            #pragma unroll
            for (int nj = 0; nj < 4; nj++)
                MMA16816H(acc[mi][nj], ah[mi], bf[nj][0], bf[nj][1]);
        #pragma unroll
        for (int mi = 0; mi < 4; mi++)
            #pragma unroll
            for (int nj = 0; nj < 4; nj++)
                MMA16816H(acc[mi][nj], al[mi], bf[nj][0], bf[nj][1]);
    };

    // prologue: fill stage 0
    cpasync_b(0, 0);
    ldg_half(0, 0); sts_half(0, 0);
    ldg_half(0, 1); sts_half(0, 1);
    CP_WAIT0();
    __syncthreads();

    for (int i = 0; i < NSTAGE; i++) {
        int b = i & 1;
        if (i + 1 < NSTAGE) {
            cpasync_b(i + 1, b ^ 1);
            ldg_half(i + 1, 0);
        }
        compute_kk(b, 0);
        compute_kk(b, 1);
        if (i + 1 < NSTAGE) {
            sts_half(b ^ 1, 0);
            ldg_half(i + 1, 1);
        }
        compute_kk(b, 2);
        compute_kk(b, 3);
        if (i + 1 < NSTAGE) {
            sts_half(b ^ 1, 1);
            CP_WAIT0();
        }
        __syncthreads();
    }

    if (phase == 0) {
        // epilogue 1: Z = scale[m]*acc ; transpose through smem ; write fp16 B2 chunks
        float* sT = reinterpret_cast<float*>(sb);   // [64 n-local][pitch 132 m-local]
        #pragma unroll
        for (int mi = 0; mi < 4; mi++) {
            int r = wm + mi * 16 + (lid >> 2);        // m-local 0..127
            float s0 = g_scale[mb + r];
            float s1 = g_scale[mb + r + 8];
            #pragma unroll
            for (int nj = 0; nj < 4; nj++) {
                int c = wn + nj * 8 + (lid & 3) * 2;  // n-local 0..63
                sT[c * 132 + r]             = acc[mi][nj][0] * s0;
                sT[(c + 1) * 132 + r]       = acc[mi][nj][1] * s0;
                sT[c * 132 + r + 8]         = acc[mi][nj][2] * s1;
                sT[(c + 1) * 132 + r + 8]   = acc[mi][nj][3] * s1;
            }
        }
        __syncthreads();
        // write 2 chunks (m-local 0..63 -> chunk 2*bx, 64..127 -> 2*bx+1), n rows nb..nb+63
        #pragma unroll 4
        for (int w = 0; w < 32; w++) {
            int idx = tid + w * 128;        // 0..4095
            int cc  = idx >> 11;            // chunk half
            int rem = idx & 2047;
            int nl  = rem >> 5;             // 0..63
            int kp  = rem & 31;             // k-pair 0..31
            float v0 = sT[nl * 132 + cc * 64 + kp * 2];
            float v1 = sT[nl * 132 + cc * 64 + kp * 2 + 1];
            uint32_t o = swz128((uint32_t)((nb + nl) * 128 + kp * 4));
            *(uint32_t*)(g_B2 + (size_t)(blockIdx.x * 2 + cc) * CHUNK_BYTES + o) =
                pack_h2(__float2half_rn(v0), __float2half_rn(v1));
        }
    } else {
        // epilogue 2: out = acc + bias
        #pragma unroll
        for (int mi = 0; mi < 4; mi++) {
            int r = mb + wm + mi * 16 + (lid >> 2);
            #pragma unroll
            for (int nj = 0; nj < 4; nj++) {
                int c = nb + wn + nj * 8 + (lid & 3) * 2;
                float2 bb = *reinterpret_cast<const float2*>(bias + c);
                *reinterpret_cast<float2*>(out + (size_t)r * FEAT + c) =
                    make_float2(acc[mi][nj][0] + bb.x, acc[mi][nj][1] + bb.y);
                *reinterpret_cast<float2*>(out + (size_t)(r + 8) * FEAT + c) =
                    make_float2(acc[mi][nj][2] + bb.x, acc[mi][nj][3] + bb.y);
            }
        }
    }
}

// ============================ launch ============================
extern "C" void kernel_launch(void* const* d_in, const int* in_sizes, int n_in,
                              void* d_out, int out_size) {
    const float* x      = (const float*)d_in[0];
    const float* d_list = (const float*)d_in[1];
    const float* U      = (const float*)d_in[2];
    const float* Vt     = (const float*)d_in[3];
    const float* W      = (const float*)d_in[4];
    const float* filt   = (const float*)d_in[5];
    const float* bias   = (const float*)d_in[6];
    float* out = (float*)d_out;

    cudaFuncSetAttribute(xw_kernel, cudaFuncAttributeMaxDynamicSharedMemorySize, 98304);
    cudaFuncSetAttribute(gemm_fused_kernel, cudaFuncAttributeMaxDynamicSharedMemorySize, 2 * STG + 1024);

    xw_kernel<<<128, 256, 98304>>>(x, W);                               // idx 0
    scale_kernel<<<32, 256>>>(d_list, filt);                            // idx 1
    scale_kernel<<<32, 256>>>(d_list, filt);                            // idx 2 (shim)
    gemm_fused_kernel<<<dim3(64, 2), 128, 2 * STG + 1024>>>(Vt, bias, out, 0);  // idx 3
    scale_kernel<<<32, 256>>>(d_list, filt);                            // idx 4 (shim)
    gemm_fused_kernel<<<dim3(64, 2), 128, 2 * STG + 1024>>>(U, bias, out, 1);   // idx 5
}

// round 9
// speedup vs baseline: 2.2252x; 2.2252x over previous
#include <cuda_runtime.h>
#include <cuda_fp16.h>
#include <cstdint>

// ============================ PTX helpers (non-'a' target safe) ============================
__device__ __forceinline__ uint32_t smem_to_u32(const void* smem_ptr) {
    uint32_t addr;
    asm("{ .reg .u64 tmp; cvta.to.shared.u64 tmp, %1; cvt.u32.u64 %0, tmp; }"
        : "=r"(addr) : "l"(smem_ptr));
    return addr;
}

#define CP_ASYNC16(dst_u32, src_ptr) \
    asm volatile("cp.async.cg.shared.global [%0], [%1], 16;" \
                 :: "r"(dst_u32), "l"(src_ptr) : "memory")
#define CP_COMMIT() asm volatile("cp.async.commit_group;" ::: "memory")
#define CP_WAIT0()  asm volatile("cp.async.wait_group 0;" ::: "memory")

#define LDSM_X4(r0, r1, r2, r3, addr) \
    asm volatile("ldmatrix.sync.aligned.m8n8.x4.shared.b16 {%0,%1,%2,%3}, [%4];" \
                 : "=r"(r0), "=r"(r1), "=r"(r2), "=r"(r3) : "r"(addr))

#define MMA16816H(d, a, b0, b1) \
    asm volatile("mma.sync.aligned.m16n8k16.row.col.f32.f16.f16.f32 " \
                 "{%0,%1,%2,%3}, {%4,%5,%6,%7}, {%8,%9}, {%0,%1,%2,%3};" \
                 : "+f"((d)[0]), "+f"((d)[1]), "+f"((d)[2]), "+f"((d)[3]) \
                 : "r"((a)[0]), "r"((a)[1]), "r"((a)[2]), "r"((a)[3]), \
                   "r"(b0), "r"(b1))

__device__ __forceinline__ uint32_t swz128(uint32_t off) {
    return off ^ ((off >> 3) & 0x70);
}
__device__ __forceinline__ uint32_t pack_h2(__half a, __half b) {
    __half2 t = __halves2half2(a, b);  // a -> low 16 bits
    return *reinterpret_cast<uint32_t*>(&t);
}

// ============================ problem constants ============================
static constexpr int NTOK   = 8192;
static constexpr int FEAT   = 128;
static constexpr int KC     = 64;               // k per B-chunk
static constexpr int NCHUNK = NTOK / KC;        // 128
static constexpr int CHUNK_BYTES = FEAT * 128;  // 128 n-rows x 128B (64 k fp16) = 16384
static constexpr int TM     = 128;              // CTA M tile
static constexpr int KSPLIT = 2;
static constexpr int KPER   = NTOK / KSPLIT;    // 4096
static constexpr int KSTEP  = 64;
static constexpr int NSTAGE = KPER / KSTEP;     // 64
// stage: [0,16K) A_hi | [16K,32K) A_lo | [32K,48K) B fp16
static constexpr int STG    = 49152;

// ============================ device scratch ============================
__device__ __align__(16) unsigned char g_B1[NCHUNK * CHUNK_BYTES];  // 2 MB fp16 xw^T chunks
__device__ __align__(16) unsigned char g_B2[NCHUNK * CHUNK_BYTES];  // 2 MB fp16 Z^T chunks
__device__ __align__(16) float g_part[KSPLIT * NTOK * FEAT];        // 8 MB partials
__device__ __align__(16) float g_scale[NTOK];

// ============================ kernel 1: xw = x @ W -> fp16 chunks ============================
__global__ void xw_kernel(const float* __restrict__ x, const float* __restrict__ W) {
    extern __shared__ float sh[];
    float* Ws = sh;             // 128*128
    float* xs = sh + 16384;     // 64*128
    const int tid = threadIdx.x;
    const int rowbase = blockIdx.x * 64;

    for (int i = tid; i < 16384; i += 256) Ws[i] = W[i];
    for (int i = tid; i < 8192;  i += 256) xs[i] = x[(size_t)rowbase * 128 + i];
    __syncthreads();

    const int n  = tid & 127;
    const int rg = tid >> 7;
    #pragma unroll 1
    for (int rp = 0; rp < 16; rp++) {
        const int r0 = rg * 32 + 2 * rp;
        float a0 = 0.f, a1 = 0.f;
        const float* x0 = xs + r0 * 128;
        const float* x1 = x0 + 128;
        #pragma unroll 8
        for (int k = 0; k < 128; k++) {
            float w = Ws[k * 128 + n];
            a0 = fmaf(x0[k], w, a0);
            a1 = fmaf(x1[k], w, a1);
        }
        int kg = rowbase + r0;
        int chunk = kg >> 6;
        int c = kg & 63;
        uint32_t off = swz128((uint32_t)n * 128u + (uint32_t)c * 2u);
        *(uint32_t*)(g_B1 + (size_t)chunk * CHUNK_BYTES + off) =
            pack_h2(__float2half_rn(a0), __float2half_rn(a1));
    }
}

// ============================ kernel 2: scale = sum_j d^2 * f ============================
__global__ void scale_kernel(const float* __restrict__ d_list, const float* __restrict__ filt) {
    int n = blockIdx.x * 256 + threadIdx.x;
    float s = 0.f;
    #pragma unroll
    for (int j = 0; j < 3; j++) {
        float d = d_list[j * NTOK + n];
        float f = filt[j * NTOK + n];
        s = fmaf(d * d, f, s);
    }
    g_scale[n] = s;
}

// ============================ GEMM: CTA 128x128, warps 4m x 2n (32x64), fp16 2-prod, K-split 2 ============================
// grid (64, 2), block 256 (8 warps, 2 per SMSP), smem 2 x 48KB stages
__global__ __launch_bounds__(256, 1)
void gemm_ksplit_kernel(const float* __restrict__ A, int phase) {
    extern __shared__ unsigned char dynsmem[];

    const unsigned char* B = phase ? g_B2 : g_B1;

    const int tid = threadIdx.x;
    const int wid = tid >> 5;
    const int lid = tid & 31;
    const int mb = blockIdx.x * TM;
    const int ks = blockIdx.y;
    const int kbase = ks * KPER;
    const int chunk0 = ks * NSTAGE;

    const int wm = (wid >> 1) * 32;   // 0,32,64,96
    const int wn = (wid & 1) * 64;    // 0,64

    uint32_t smem_u = smem_to_u32(dynsmem);
    uint32_t base = (smem_u + 1023u) & ~1023u;
    unsigned char* sb = dynsmem + (base - smem_u);

    float acc[2][8][4];   // mi (m16) x nj (n8) x 4
    #pragma unroll
    for (int i = 0; i < 2; i++)
        #pragma unroll
        for (int j = 0; j < 8; j++)
            #pragma unroll
            for (int q = 0; q < 4; q++) acc[i][j][q] = 0.f;

    float4 aReg[8];   // A stage: 128 rows x 64 k fp32 = 2048 float4 / 256 thr

    auto ldg_stage = [&](int s) {
        #pragma unroll
        for (int i = 0; i < 8; i++) {
            int idx = tid + i * 256;
            int row = idx >> 4;
            int c4 = idx & 15;
            const float* src = A + (size_t)(mb + row) * NTOK + kbase + s * KSTEP + c4 * 4;
            aReg[i] = *reinterpret_cast<const float4*>(src);
        }
    };
    auto sts_a = [&](int st) {
        unsigned char* stp = sb + st * STG;
        #pragma unroll
        for (int i = 0; i < 8; i++) {
            int idx = tid + i * 256;
            int row = idx >> 4;
            int c4 = idx & 15;
            uint32_t o = swz128((uint32_t)(row * 128 + c4 * 8));
            float4 v = aReg[i];
            __half hx = __float2half_rn(v.x);
            __half hy = __float2half_rn(v.y);
            __half hz = __float2half_rn(v.z);
            __half hw = __float2half_rn(v.w);
            __half lx = __float2half_rn(v.x - __half2float(hx));
            __half ly = __float2half_rn(v.y - __half2float(hy));
            __half lz = __float2half_rn(v.z - __half2float(hz));
            __half lw = __float2half_rn(v.w - __half2float(hw));
            *(uint2*)(stp + o)         = make_uint2(pack_h2(hx, hy), pack_h2(hz, hw));
            *(uint2*)(stp + 16384 + o) = make_uint2(pack_h2(lx, ly), pack_h2(lz, lw));
        }
    };
    auto cpasync_b = [&](int s, int st) {
        uint32_t dst = base + st * STG + 32768;
        const unsigned char* src = B + (size_t)(chunk0 + s) * CHUNK_BYTES;
        #pragma unroll
        for (int i = 0; i < 4; i++) {
            int off = (tid + i * 256) * 16;
            CP_ASYNC16(dst + off, src + off);
        }
        CP_COMMIT();
    };

    // ldmatrix per-lane address components
    const int l7  = lid & 7;
    const int mat = lid >> 3;
    const int a_row_off = l7 + (mat & 1) * 8;
    const int a_kb_add  = (mat >> 1) * 16;
    const int b_row_off = l7 + (mat >> 1) * 8;
    const int b_kb_add  = (mat & 1) * 16;

    auto compute_stage = [&](int st) {
        uint32_t sA = base + st * STG;
        uint32_t sB = sA + 32768;
        #pragma unroll
        for (int kk = 0; kk < 4; kk++) {
            const int kb = kk * 32;
            uint32_t ah[2][4], al[2][4], bf[8][2];
            // B frags: 4 x LDSM_X4 covering n64 x k16
            #pragma unroll
            for (int g = 0; g < 4; g++) {
                int row = wn + g * 16 + b_row_off;
                uint32_t off = (uint32_t)(row * 128) + (uint32_t)((kb + b_kb_add) ^ ((row & 7) << 4));
                uint32_t r0, r1, r2, r3;
                LDSM_X4(r0, r1, r2, r3, sB + off);
                bf[2 * g][0] = r0;     bf[2 * g][1] = r1;
                bf[2 * g + 1][0] = r2; bf[2 * g + 1][1] = r3;
            }
            // A frags hi + lo
            #pragma unroll
            for (int mi = 0; mi < 2; mi++) {
                int row = wm + mi * 16 + a_row_off;
                uint32_t off = (uint32_t)(row * 128) + (uint32_t)((kb + a_kb_add) ^ ((row & 7) << 4));
                LDSM_X4(ah[mi][0], ah[mi][1], ah[mi][2], ah[mi][3], sA + off);
                LDSM_X4(al[mi][0], al[mi][1], al[mi][2], al[mi][3], sA + 16384 + off);
            }
            // hi products then lo products
            #pragma unroll
            for (int mi = 0; mi < 2; mi++)
                #pragma unroll
                for (int nj = 0; nj < 8; nj++)
                    MMA16816H(acc[mi][nj], ah[mi], bf[nj][0], bf[nj][1]);
            #pragma unroll
            for (int mi = 0; mi < 2; mi++)
                #pragma unroll
                for (int nj = 0; nj < 8; nj++)
                    MMA16816H(acc[mi][nj], al[mi], bf[nj][0], bf[nj][1]);
        }
    };

    // prologue
    ldg_stage(0);
    cpasync_b(0, 0);
    sts_a(0);
    CP_WAIT0();
    __syncthreads();

    for (int i = 0; i < NSTAGE; i++) {
        int b = i & 1;
        if (i + 1 < NSTAGE) {
            ldg_stage(i + 1);
            cpasync_b(i + 1, b ^ 1);
        }
        compute_stage(b);
        if (i + 1 < NSTAGE) {
            sts_a(b ^ 1);
            CP_WAIT0();
        }
        __syncthreads();
    }

    // epilogue: write fp32 partials
    float* P = g_part + (size_t)ks * (NTOK * FEAT);
    #pragma unroll
    for (int mi = 0; mi < 2; mi++) {
        int r = mb + wm + mi * 16 + (lid >> 2);
        #pragma unroll
        for (int nj = 0; nj < 8; nj++) {
            int c = wn + nj * 8 + (lid & 3) * 2;
            *reinterpret_cast<float2*>(P + (size_t)r * FEAT + c) =
                make_float2(acc[mi][nj][0], acc[mi][nj][1]);
            *reinterpret_cast<float2*>(P + (size_t)(r + 8) * FEAT + c) =
                make_float2(acc[mi][nj][2], acc[mi][nj][3]);
        }
    }
}

// ============================ reduce1: combine splits, scale, write fp16 Z^T chunks ============================
__global__ void reduce1_kernel() {
    const int n = threadIdx.x;
    const int m0 = blockIdx.x * 2;
    const float s0 = g_scale[m0];
    const float s1 = g_scale[m0 + 1];
    const float* P0 = g_part;
    const float* P1 = g_part + NTOK * FEAT;
    float v0 = (P0[(size_t)m0 * FEAT + n] + P1[(size_t)m0 * FEAT + n]) * s0;
    float v1 = (P0[(size_t)(m0 + 1) * FEAT + n] + P1[(size_t)(m0 + 1) * FEAT + n]) * s1;
    int chunk = m0 >> 6;
    int c = m0 & 63;
    uint32_t off = swz128((uint32_t)n * 128u + (uint32_t)c * 2u);
    *(uint32_t*)(g_B2 + (size_t)chunk * CHUNK_BYTES + off) =
        pack_h2(__float2half_rn(v0), __float2half_rn(v1));
}

// ============================ reduce2: out = P0 + P1 + bias ============================
__global__ void reduce2_kernel(const float* __restrict__ bias, float* __restrict__ out) {
    int idx = blockIdx.x * 256 + threadIdx.x;
    const float4* P0 = reinterpret_cast<const float4*>(g_part);
    const float4* P1 = reinterpret_cast<const float4*>(g_part + NTOK * FEAT);
    float4 a = P0[idx];
    float4 b = P1[idx];
    float4 bb = reinterpret_cast<const float4*>(bias)[idx & 31];
    float4 r;
    r.x = a.x + b.x + bb.x;
    r.y = a.y + b.y + bb.y;
    r.z = a.z + b.z + bb.z;
    r.w = a.w + b.w + bb.w;
    reinterpret_cast<float4*>(out)[idx] = r;
}

// ============================ launch ============================
extern "C" void kernel_launch(void* const* d_in, const int* in_sizes, int n_in,
                              void* d_out, int out_size) {
    const float* x      = (const float*)d_in[0];
    const float* d_list = (const float*)d_in[1];
    const float* U      = (const float*)d_in[2];
    const float* Vt     = (const float*)d_in[3];
    const float* W      = (const float*)d_in[4];
    const float* filt   = (const float*)d_in[5];
    const float* bias   = (const float*)d_in[6];
    float* out = (float*)d_out;

    cudaFuncSetAttribute(xw_kernel, cudaFuncAttributeMaxDynamicSharedMemorySize, 98304);
    cudaFuncSetAttribute(gemm_ksplit_kernel, cudaFuncAttributeMaxDynamicSharedMemorySize, 2 * STG + 1024);

    xw_kernel<<<128, 256, 98304>>>(x, W);                                  // idx 0
    scale_kernel<<<32, 256>>>(d_list, filt);                               // idx 1
    scale_kernel<<<32, 256>>>(d_list, filt);                               // idx 2 (shim)
    gemm_ksplit_kernel<<<dim3(64, 2), 256, 2 * STG + 1024>>>(Vt, 0);       // idx 3
    reduce1_kernel<<<4096, 128>>>();                                       // idx 4
    gemm_ksplit_kernel<<<dim3(64, 2), 256, 2 * STG + 1024>>>(U, 1);        // idx 5  <- ncu -s 5
    reduce2_kernel<<<1024, 256>>>(bias, out);                              // idx 6
}